// round 1
// baseline (speedup 1.0000x reference)
#include <cuda_runtime.h>

#define IMG_W 512
#define IMG_H 512
#define ROWS  16
#define NTHREADS 128   // 128 threads * 4 cols = 512 = full row width

struct RowData {
    float  l;    // column x-1 of this thread's first column
    float4 v;    // columns x .. x+3
    float  r;    // column x+4
};

__device__ __forceinline__ float med3(float a, float b, float c) {
    return fmaxf(fminf(a, b), fminf(fmaxf(a, b), c));
}
__device__ __forceinline__ float max3(float a, float b, float c) {
    return fmaxf(fmaxf(a, b), c);
}
__device__ __forceinline__ float min3(float a, float b, float c) {
    return fminf(fminf(a, b), c);
}
__device__ __forceinline__ void sort3(float a, float b, float c,
                                      float& lo, float& mi, float& hi) {
    float t1 = fminf(a, b);
    float t2 = fmaxf(a, b);
    lo = fminf(t1, c);
    hi = fmaxf(t2, c);
    mi = fmaxf(t1, fminf(t2, c));
}

__device__ __forceinline__ RowData load_row(const float* __restrict__ img,
                                            int y, int tid) {
    // reflect (no edge repeat): -1 -> 1, H -> H-2
    int yy = y;
    if (yy < 0)           yy = -yy;
    else if (yy >= IMG_H) yy = 2 * IMG_H - 2 - yy;

    const float4* p = reinterpret_cast<const float4*>(img + (size_t)yy * IMG_W);
    float4 v = __ldg(&p[tid]);

    RowData row;
    row.v = v;
    row.l = __shfl_up_sync(0xffffffffu, v.w, 1);
    row.r = __shfl_down_sync(0xffffffffu, v.x, 1);

    int lane = tid & 31;
    int x4   = tid << 2;
    if (lane == 0) {
        int xl = (x4 == 0) ? 1 : (x4 - 1);
        row.l = __ldg(img + (size_t)yy * IMG_W + xl);
    }
    if (lane == 31) {
        int xr = (x4 + 4 >= IMG_W) ? (IMG_W - 2) : (x4 + 4);
        row.r = __ldg(img + (size_t)yy * IMG_W + xr);
    }
    return row;
}

__global__ __launch_bounds__(NTHREADS)
void MedianFilter2D_68745246540291_kernel(const float* __restrict__ in,
                                          float* __restrict__ out) {
    const int tid    = threadIdx.x;          // 0..127
    const int stripe = blockIdx.x & 31;      // 32 stripes of 16 rows
    const int plane  = blockIdx.x >> 5;      // 48 planes (B*C)

    const float* img  = in  + (size_t)plane * IMG_H * IMG_W;
    float*       oimg = out + (size_t)plane * IMG_H * IMG_W;

    const int y0 = stripe * ROWS;

    RowData rA = load_row(img, y0 - 1, tid);
    RowData rB = load_row(img, y0,     tid);

#pragma unroll 4
    for (int i = 0; i < ROWS; i++) {
        const int y = y0 + i;
        RowData rC = load_row(img, y + 1, tid);

        float a0 = rA.l, a1 = rA.v.x, a2 = rA.v.y, a3 = rA.v.z, a4 = rA.v.w, a5 = rA.r;
        float b0 = rB.l, b1 = rB.v.x, b2 = rB.v.y, b3 = rB.v.z, b4 = rB.v.w, b5 = rB.r;
        float c0 = rC.l, c1 = rC.v.x, c2 = rC.v.y, c3 = rC.v.z, c4 = rC.v.w, c5 = rC.r;

        float lo0, mi0, hi0, lo1, mi1, hi1, lo2, mi2, hi2;
        float lo3, mi3, hi3, lo4, mi4, hi4, lo5, mi5, hi5;
        sort3(a0, b0, c0, lo0, mi0, hi0);
        sort3(a1, b1, c1, lo1, mi1, hi1);
        sort3(a2, b2, c2, lo2, mi2, hi2);
        sort3(a3, b3, c3, lo3, mi3, hi3);
        sort3(a4, b4, c4, lo4, mi4, hi4);
        sort3(a5, b5, c5, lo5, mi5, hi5);

        float4 o;
        o.x = med3(max3(lo0, lo1, lo2), med3(mi0, mi1, mi2), min3(hi0, hi1, hi2));
        o.y = med3(max3(lo1, lo2, lo3), med3(mi1, mi2, mi3), min3(hi1, hi2, hi3));
        o.z = med3(max3(lo2, lo3, lo4), med3(mi2, mi3, mi4), min3(hi2, hi3, hi4));
        o.w = med3(max3(lo3, lo4, lo5), med3(mi3, mi4, mi5), min3(hi3, hi4, hi5));

        reinterpret_cast<float4*>(oimg + (size_t)y * IMG_W)[tid] = o;

        rA = rB;
        rB = rC;
    }
}

extern "C" void kernel_launch(void* const* d_in, const int* in_sizes, int n_in,
                              void* d_out, int out_size) {
    const float* in  = (const float*)d_in[0];
    float*       out = (float*)d_out;

    // 16 * 3 = 48 planes, 32 row-stripes per plane
    dim3 grid(48 * 32);
    dim3 block(NTHREADS);
    MedianFilter2D_68745246540291_kernel<<<grid, block>>>(in, out);
}

// round 2
// speedup vs baseline: 1.0769x; 1.0769x over previous
#include <cuda_runtime.h>

#define IMG_W 512
#define IMG_H 512
#define ROWS  16
#define NTHREADS 128   // 128 threads * 4 cols = 512 = full row width

// Per-row horizontally-sorted triples for this thread's 4 columns.
struct Sorted {
    float lo[4], mi[4], hi[4];
};

__device__ __forceinline__ void sort3(float a, float b, float c,
                                      float& lo, float& mi, float& hi) {
    float t1 = fminf(a, b);
    float t2 = fmaxf(a, b);
    lo = fminf(t1, c);
    hi = fmaxf(t2, c);
    mi = fmaxf(t1, fminf(t2, c));
}
__device__ __forceinline__ float med3(float a, float b, float c) {
    float t1 = fminf(a, b);
    float t2 = fmaxf(a, b);
    return fmaxf(t1, fminf(t2, c));
}
__device__ __forceinline__ float max3(float a, float b, float c) {
    return fmaxf(fmaxf(a, b), c);
}
__device__ __forceinline__ float min3(float a, float b, float c) {
    return fminf(fminf(a, b), c);
}

// Load one raw input row (reflect-padded vertically) and produce the
// horizontally-sorted triples for this thread's 4 columns.
__device__ __forceinline__ Sorted load_hsort(const float* __restrict__ img,
                                             int y, int tid) {
    // reflect (no edge repeat): -1 -> 1, H -> H-2
    int yy = (y < 0) ? -y : ((y >= IMG_H) ? (2 * IMG_H - 2 - y) : y);

    const float4* p = reinterpret_cast<const float4*>(img + (size_t)yy * IMG_W);
    float4 v = __ldg(&p[tid]);

    float l = __shfl_up_sync(0xffffffffu, v.w, 1);
    float r = __shfl_down_sync(0xffffffffu, v.x, 1);

    const int lane = tid & 31;
    const int x4   = tid << 2;
    if (lane == 0) {
        // reflect at x=0: left neighbor of col 0 is col 1
        l = __ldg(img + (size_t)yy * IMG_W + (x4 ? (x4 - 1) : 1));
    }
    if (lane == 31) {
        // reflect at x=W-1: right neighbor is col W-2
        r = __ldg(img + (size_t)yy * IMG_W + ((x4 + 4 < IMG_W) ? (x4 + 4) : (IMG_W - 2)));
    }

    Sorted s;
    sort3(l,   v.x, v.y, s.lo[0], s.mi[0], s.hi[0]);
    sort3(v.x, v.y, v.z, s.lo[1], s.mi[1], s.hi[1]);
    sort3(v.y, v.z, v.w, s.lo[2], s.mi[2], s.hi[2]);
    sort3(v.z, v.w, r,   s.lo[3], s.mi[3], s.hi[3]);
    return s;
}

__global__ __launch_bounds__(NTHREADS)
void MedianFilter2D_68745246540291_kernel(const float* __restrict__ in,
                                          float* __restrict__ out) {
    const int tid    = threadIdx.x;          // 0..127
    const int stripe = blockIdx.x & 31;      // 32 stripes of 16 rows
    const int plane  = blockIdx.x >> 5;      // 48 planes (B*C)

    const float* img  = in  + (size_t)plane * IMG_H * IMG_W;
    float*       oimg = out + (size_t)plane * IMG_H * IMG_W;

    const int y0 = stripe * ROWS;

    // Rolling 3-row window of horizontally presorted triples.
    Sorted S[3];
    S[0] = load_hsort(img, y0 - 1, tid);
    S[1] = load_hsort(img, y0,     tid);

    float4* orow = reinterpret_cast<float4*>(oimg + (size_t)y0 * IMG_W) + tid;

#pragma unroll
    for (int i = 0; i < ROWS; i++) {
        S[(i + 2) % 3] = load_hsort(img, y0 + i + 1, tid);

        const Sorted& A = S[i % 3];
        const Sorted& B = S[(i + 1) % 3];
        const Sorted& C = S[(i + 2) % 3];

        float4 o;
        o.x = med3(max3(A.lo[0], B.lo[0], C.lo[0]),
                   med3(A.mi[0], B.mi[0], C.mi[0]),
                   min3(A.hi[0], B.hi[0], C.hi[0]));
        o.y = med3(max3(A.lo[1], B.lo[1], C.lo[1]),
                   med3(A.mi[1], B.mi[1], C.mi[1]),
                   min3(A.hi[1], B.hi[1], C.hi[1]));
        o.z = med3(max3(A.lo[2], B.lo[2], C.lo[2]),
                   med3(A.mi[2], B.mi[2], C.mi[2]),
                   min3(A.hi[2], B.hi[2], C.hi[2]));
        o.w = med3(max3(A.lo[3], B.lo[3], C.lo[3]),
                   med3(A.mi[3], B.mi[3], C.mi[3]),
                   min3(A.hi[3], B.hi[3], C.hi[3]));

        *orow = o;
        orow += IMG_W / 4;
    }
}

extern "C" void kernel_launch(void* const* d_in, const int* in_sizes, int n_in,
                              void* d_out, int out_size) {
    const float* in  = (const float*)d_in[0];
    float*       out = (float*)d_out;

    // 16 * 3 = 48 planes, 32 row-stripes per plane
    dim3 grid(48 * 32);
    dim3 block(NTHREADS);
    MedianFilter2D_68745246540291_kernel<<<grid, block>>>(in, out);
}